// round 2
// baseline (speedup 1.0000x reference)
#include <cuda_runtime.h>

// Problem constants (fixed shapes per reference setup_inputs)
#define BB    4
#define HH    64
#define WW    64
#define CH    32
#define BANDS 128

// Conv tiling: 16x4 pixel tile, each thread computes 16 output channels of
// one pixel => 64 pixels * 2 channel-halves = 128 threads/block.
#define TX 16
#define TY 4
#define CONV_THREADS 128

#define PIXELS   (BB*HH*WW)                 // 16384
#define FEAT_ELEMS (PIXELS*CH)              // 524288 floats (2 MB)

// Scratch (device globals: no allocation allowed)
__device__ float d_tg[FEAT_ELEMS];
__device__ float d_tb[FEAT_ELEMS];
__device__ float d_gamma[FEAT_ELEMS];
__device__ float d_beta[FEAT_ELEMS];

// ---------------------------------------------------------------------------
// packed fp32x2 helpers (Blackwell: doubles fp32 FMA throughput; ptxas will
// not auto-fuse, must come from PTX)
// ---------------------------------------------------------------------------
static __device__ __forceinline__ unsigned long long pack2(float a) {
    unsigned int u = __float_as_uint(a);
    unsigned long long r;
    asm("mov.b64 %0, {%1, %1};" : "=l"(r) : "r"(u));
    return r;
}

static __device__ __forceinline__ void ffma2(unsigned long long& d,
                                             unsigned long long a,
                                             unsigned long long b) {
    asm("fma.rn.f32x2 %0, %1, %2, %0;" : "+l"(d) : "l"(a), "l"(b));
}

// ---------------------------------------------------------------------------
// conv3x3 SAME + bias + LeakyReLU(0.3), NHWC, HWIO weights, C=32 -> C=32
// SMEM: weights [9][32][32] (36864B) + input tile [(TY+2)][18][36] padded
// (pixel stride 36 floats keeps float4 alignment + spreads banks).
// ---------------------------------------------------------------------------
#define SW_ELEMS   (9*32*32)                // 9216
#define TILE_H     (TY+2)                   // 6
#define TILE_W     (TX+2)                   // 18
#define PIX_STRIDE 36
#define SIN_ELEMS  (TILE_H*TILE_W*PIX_STRIDE)  // 6*18*36 = 3888
#define CONV_SMEM  ((SW_ELEMS + SIN_ELEMS)*4)  // 52416 bytes

__global__ void __launch_bounds__(CONV_THREADS)
conv3x3_lrelu(const float* __restrict__ in, const float* __restrict__ w,
              const float* __restrict__ bias, float* __restrict__ out)
{
    extern __shared__ float smem[];
    float* s_w  = smem;             // [tap][ci][co] flat, co contiguous
    float* s_in = smem + SW_ELEMS;  // [(y)*18 + x]*36 + ci

    const int tid = threadIdx.x;
    const int b   = blockIdx.z;
    const int tx0 = blockIdx.x * TX;
    const int ty0 = blockIdx.y * TY;

    // ---- load weights (float4 vectorized, layout already matches) ----
    {
        const float4* wsrc = (const float4*)w;
        float4* wdst = (float4*)s_w;
        #pragma unroll 1
        for (int i = tid; i < SW_ELEMS/4; i += CONV_THREADS)
            wdst[i] = wsrc[i];
    }

    // ---- load input tile with halo (zero pad outside image) ----
    #pragma unroll 1
    for (int i = tid; i < TILE_H*TILE_W*CH; i += CONV_THREADS) {
        int ci = i & 31;
        int t  = i >> 5;
        int x  = t % TILE_W;
        int y  = t / TILE_W;
        int gx = tx0 + x - 1;
        int gy = ty0 + y - 1;
        float v = 0.0f;
        if (gx >= 0 && gx < WW && gy >= 0 && gy < HH)
            v = in[(((b*HH) + gy)*WW + gx)*CH + ci];
        s_in[(y*TILE_W + x)*PIX_STRIDE + ci] = v;
    }
    __syncthreads();

    // ---- per-thread assignment ----
    const int p  = tid & 63;          // pixel within 16x4 tile
    const int px = p & 15;
    const int py = p >> 4;
    const int co = (tid >> 6) << 4;   // 0 or 16: this thread's 16 out channels

    unsigned long long acc[8];
    #pragma unroll
    for (int j = 0; j < 8; j++) acc[j] = 0ull;

    const float* ipbase = &s_in[(py*TILE_W + px)*PIX_STRIDE];

    #pragma unroll 1
    for (int kh = 0; kh < 3; kh++) {
        #pragma unroll 1
        for (int kw = 0; kw < 3; kw++) {
            const float* ip = ipbase + (kh*TILE_W + kw)*PIX_STRIDE;
            // fetch all 32 input channels of this tap into registers
            float a[32];
            #pragma unroll
            for (int k = 0; k < 8; k++) {
                float4 v = *(const float4*)(ip + 4*k);
                a[4*k+0] = v.x; a[4*k+1] = v.y; a[4*k+2] = v.z; a[4*k+3] = v.w;
            }
            // weights for this tap: s_w[tap][ci][co..co+15]; uniform across
            // the warp => broadcast LDS, conflict-free
            const unsigned long long* wp =
                (const unsigned long long*)&s_w[((kh*3 + kw) << 10) + co];
            #pragma unroll
            for (int ci = 0; ci < 32; ci++) {
                unsigned long long a2 = pack2(a[ci]);
                const ulonglong2* wv = (const ulonglong2*)(wp + ci*16);
                ulonglong2 w0 = wv[0];
                ulonglong2 w1 = wv[1];
                ulonglong2 w2 = wv[2];
                ulonglong2 w3 = wv[3];
                ffma2(acc[0], a2, w0.x); ffma2(acc[1], a2, w0.y);
                ffma2(acc[2], a2, w1.x); ffma2(acc[3], a2, w1.y);
                ffma2(acc[4], a2, w2.x); ffma2(acc[5], a2, w2.y);
                ffma2(acc[6], a2, w3.x); ffma2(acc[7], a2, w3.y);
            }
        }
    }

    // ---- epilogue: bias + LeakyReLU(0.3), store 16 floats ----
    const int gx = tx0 + px;
    const int gy = ty0 + py;
    float* op = &out[(((b*HH) + gy)*WW + gx)*CH + co];
    #pragma unroll
    for (int j = 0; j < 8; j++) {
        unsigned int lo, hi;
        asm("mov.b64 {%0, %1}, %2;" : "=r"(lo), "=r"(hi) : "l"(acc[j]));
        float y0 = __uint_as_float(lo) + __ldg(&bias[co + 2*j]);
        float y1 = __uint_as_float(hi) + __ldg(&bias[co + 2*j + 1]);
        op[2*j]     = (y0 < 0.0f) ? 0.3f*y0 : y0;
        op[2*j + 1] = (y1 < 0.0f) ? 0.3f*y1 : y1;
    }
}

// ---------------------------------------------------------------------------
// FiLM: out[b,h,w,band,c] = x * gamma[b,h,w,c] + beta[b,h,w,c]
// float4 vectorized; gamma/beta are 2 MB each => L2-resident, L1 broadcast.
// ---------------------------------------------------------------------------
#define OUT_FLOAT4 (BB*HH*WW*BANDS*CH/4)    // 16,777,216

__global__ void __launch_bounds__(256)
film_kernel(const float4* __restrict__ x, const float4* __restrict__ g,
            const float4* __restrict__ be, float4* __restrict__ out)
{
    unsigned int q = blockIdx.x * 256u + threadIdx.x;
    if (q >= OUT_FLOAT4) return;
    // float4s per pixel = BANDS*CH/4 = 1024; C/4 = 8 float4 of gamma per pixel
    unsigned int gi = ((q >> 10) << 3) | (q & 7u);
    float4 xv = __ldg(x + q);
    float4 gv = __ldg(g + gi);
    float4 bv = __ldg(be + gi);
    float4 o;
    o.x = fmaf(xv.x, gv.x, bv.x);
    o.y = fmaf(xv.y, gv.y, bv.y);
    o.z = fmaf(xv.z, gv.z, bv.z);
    o.w = fmaf(xv.w, gv.w, bv.w);
    out[q] = o;
}

// ---------------------------------------------------------------------------
// launch (graph-capturable: kernel launches + immediate attribute/symbol APIs)
// ---------------------------------------------------------------------------
extern "C" void kernel_launch(void* const* d_in, const int* in_sizes, int n_in,
                              void* d_out, int out_size)
{
    (void)in_sizes; (void)n_in; (void)out_size;
    const float* x   = (const float*)d_in[0];
    const float* psi = (const float*)d_in[1];
    const float* gw1 = (const float*)d_in[2];
    const float* gb1 = (const float*)d_in[3];
    const float* gw2 = (const float*)d_in[4];
    const float* gb2 = (const float*)d_in[5];
    const float* bw1 = (const float*)d_in[6];
    const float* bb1 = (const float*)d_in[7];
    const float* bw2 = (const float*)d_in[8];
    const float* bb2 = (const float*)d_in[9];

    float *tg, *tb, *gm, *bt;
    cudaGetSymbolAddress((void**)&tg, d_tg);
    cudaGetSymbolAddress((void**)&tb, d_tb);
    cudaGetSymbolAddress((void**)&gm, d_gamma);
    cudaGetSymbolAddress((void**)&bt, d_beta);

    cudaFuncSetAttribute(conv3x3_lrelu,
                         cudaFuncAttributeMaxDynamicSharedMemorySize,
                         CONV_SMEM);

    dim3 cgrid(WW/TX, HH/TY, BB);   // (4, 16, 4) = 256 blocks

    // stage 1: psi -> tg, tb (independent)
    conv3x3_lrelu<<<cgrid, CONV_THREADS, CONV_SMEM>>>(psi, gw1, gb1, tg);
    conv3x3_lrelu<<<cgrid, CONV_THREADS, CONV_SMEM>>>(psi, bw1, bb1, tb);
    // stage 2: tg -> gamma, tb -> beta
    conv3x3_lrelu<<<cgrid, CONV_THREADS, CONV_SMEM>>>(tg, gw2, gb2, gm);
    conv3x3_lrelu<<<cgrid, CONV_THREADS, CONV_SMEM>>>(tb, bw2, bb2, bt);

    // FiLM modulation (HBM-bound streaming)
    film_kernel<<<OUT_FLOAT4/256, 256>>>((const float4*)x, (const float4*)gm,
                                         (const float4*)bt, (float4*)d_out);
}

// round 5
// speedup vs baseline: 1.4603x; 1.4603x over previous
#include <cuda_runtime.h>

// Problem constants (fixed shapes per reference setup_inputs)
#define BB    4
#define HH    64
#define WW    64
#define CH    32
#define BANDS 128

#define PIXELS     (BB*HH*WW)            // 16384
#define FEAT_ELEMS (PIXELS*CH)           // 524288 floats (2 MB)

// Scratch (device globals: no allocation allowed)
__device__ float d_tg[FEAT_ELEMS];
__device__ float d_tb[FEAT_ELEMS];
__device__ float d_gamma[FEAT_ELEMS];
__device__ float d_beta[FEAT_ELEMS];

// ---------------------------------------------------------------------------
// packed fp32x2 helpers (sm_100a: 2x fp32 FMA throughput; only via PTX)
// ---------------------------------------------------------------------------
static __device__ __forceinline__ unsigned long long pack2(float a) {
    unsigned int u = __float_as_uint(a);
    unsigned long long r;
    asm("mov.b64 %0, {%1, %1};" : "=l"(r) : "r"(u));
    return r;
}
static __device__ __forceinline__ void ffma2(unsigned long long& d,
                                             unsigned long long a,
                                             unsigned long long b) {
    asm("fma.rn.f32x2 %0, %1, %2, %0;" : "+l"(d) : "l"(a), "l"(b));
}
static __device__ __forceinline__ float lrelu(float v) {
    return (v < 0.0f) ? 0.3f * v : v;
}

// ---------------------------------------------------------------------------
// conv3x3 SAME + bias + LeakyReLU(0.3), C=32->32, NHWC / HWIO.
// One kernel computes BOTH branches of a stage (branch picked by blockIdx.z).
//
// Tile: 32 wide x 4 tall outputs. 128 threads:
//   warp q = tid>>5  -> output channels co = 8q..8q+7
//   lane x = tid&31  -> output column; each thread owns 4 vertical pixels.
// Weight regs (16 u64 per ci4-chunk) reused across 4 pixels -> FMA-bound.
// SMEM: weights [9][32][32] (36.9KB) + input tile [6][34] px, stride 36 fl
// (lane stride 144B -> LDS.128 phases cover full 128B: conflict-free).
// ---------------------------------------------------------------------------
#define TIW       34
#define TIH       6
#define PSTRIDE   36
#define SW_ELEMS  (9*32*32)                          // 9216
#define SIN_ELEMS (TIH*TIW*PSTRIDE)                  // 7344
#define CONV_SMEM ((SW_ELEMS + SIN_ELEMS)*4)         // 66240 B

__global__ void __launch_bounds__(128)
conv_stage(const float* __restrict__ in_g, const float* __restrict__ in_b,
           const float* __restrict__ wg, const float* __restrict__ bg,
           const float* __restrict__ wb, const float* __restrict__ bbias,
           float* __restrict__ out_g, float* __restrict__ out_b)
{
    extern __shared__ float smem[];
    float* s_w  = smem;              // [tap][ci][co], co contiguous
    float* s_in = smem + SW_ELEMS;   // [(r*34 + c)*36 + ci]

    const int tid = threadIdx.x;
    const int x0  = blockIdx.x * 32;
    const int y0  = blockIdx.y * 4;
    const int b   = blockIdx.z & 3;
    const int br  = blockIdx.z >> 2;       // 0 = gamma, 1 = beta

    const float* in   = br ? in_b  : in_g;
    const float* w    = br ? wb    : wg;
    const float* bias = br ? bbias : bg;
    float*       out  = br ? out_b : out_g;

    // ---- stage weights into smem (layout already matches HWIO flat) ----
    {
        const float4* ws = (const float4*)w;
        float4* wd = (float4*)s_w;
        #pragma unroll 1
        for (int i = tid; i < SW_ELEMS/4; i += 128)
            wd[i] = ws[i];
    }

    // ---- stage input tile with halo (6 rows x 34 cols x 32 ch) ----
    #pragma unroll 1
    for (int i = tid; i < TIH*TIW*8; i += 128) {
        int j = i & 7;            // ci4 chunk
        int t = i >> 3;           // pixel index within tile
        int c = t % TIW;
        int r = t / TIW;
        int gx = x0 + c - 1;
        int gy = y0 + r - 1;
        float4 v = make_float4(0.f, 0.f, 0.f, 0.f);
        if (gx >= 0 && gx < WW && gy >= 0 && gy < HH)
            v = *(const float4*)&in[(((b*HH) + gy)*WW + gx)*CH + j*4];
        *(float4*)&s_in[(r*TIW + c)*PSTRIDE + j*4] = v;
    }
    __syncthreads();

    const int q = tid >> 5;       // co-quarter
    const int x = tid & 31;       // output column within tile
    const int co = q << 3;

    unsigned long long acc[4][4];
    #pragma unroll
    for (int o = 0; o < 4; o++)
        #pragma unroll
        for (int k = 0; k < 4; k++) acc[o][k] = 0ull;

    #pragma unroll 1
    for (int kh = 0; kh < 3; kh++) {
        #pragma unroll 1
        for (int c4 = 0; c4 < 8; c4++) {
            #pragma unroll
            for (int kw = 0; kw < 3; kw++) {
                // weights for (kh,kw, ci=4*c4..+3, co..co+7): 16 u64, broadcast LDS
                const ulonglong2* wp = (const ulonglong2*)
                    &s_w[((kh*3 + kw) << 10) + (c4 << 7) + co];
                ulonglong2 wv[4][2];
                #pragma unroll
                for (int ci = 0; ci < 4; ci++) {
                    wv[ci][0] = wp[ci*8];      // 32 floats per ci = 8 ull2
                    wv[ci][1] = wp[ci*8 + 1];
                }
                #pragma unroll
                for (int o = 0; o < 4; o++) {
                    float4 av = *(const float4*)
                        &s_in[((o + kh)*TIW + x + kw)*PSTRIDE + (c4 << 2)];
                    const float* af = (const float*)&av;
                    #pragma unroll
                    for (int ci = 0; ci < 4; ci++) {
                        unsigned long long a2 = pack2(af[ci]);
                        ffma2(acc[o][0], a2, wv[ci][0].x);
                        ffma2(acc[o][1], a2, wv[ci][0].y);
                        ffma2(acc[o][2], a2, wv[ci][1].x);
                        ffma2(acc[o][3], a2, wv[ci][1].y);
                    }
                }
            }
        }
    }

    // ---- epilogue: bias + LeakyReLU, store 4 rows x 8 channels ----
    float bv[8];
    #pragma unroll
    for (int k = 0; k < 8; k++) bv[k] = __ldg(&bias[co + k]);

    #pragma unroll
    for (int o = 0; o < 4; o++) {
        float r[8];
        #pragma unroll
        for (int k = 0; k < 4; k++) {
            unsigned int lo, hi;
            asm("mov.b64 {%0, %1}, %2;" : "=r"(lo), "=r"(hi) : "l"(acc[o][k]));
            r[2*k]   = lrelu(__uint_as_float(lo) + bv[2*k]);
            r[2*k+1] = lrelu(__uint_as_float(hi) + bv[2*k+1]);
        }
        float* op = &out[(((b*HH) + y0 + o)*WW + x0 + x)*CH + co];
        *(float4*)op       = make_float4(r[0], r[1], r[2], r[3]);
        *(float4*)(op + 4) = make_float4(r[4], r[5], r[6], r[7]);
    }
}

// ---------------------------------------------------------------------------
// FiLM: out[b,h,w,band,c] = x * gamma[b,h,w,c] + beta[b,h,w,c]
// Already at HBM roofline (~7.2 TB/s) — unchanged.
// ---------------------------------------------------------------------------
#define OUT_FLOAT4 (BB*HH*WW*BANDS*CH/4)    // 16,777,216

__global__ void __launch_bounds__(256)
film_kernel(const float4* __restrict__ x, const float4* __restrict__ g,
            const float4* __restrict__ be, float4* __restrict__ out)
{
    unsigned int idx = blockIdx.x * 256u + threadIdx.x;
    if (idx >= OUT_FLOAT4) return;
    unsigned int gi = ((idx >> 10) << 3) | (idx & 7u);
    float4 xv = __ldg(x + idx);
    float4 gv = __ldg(g + gi);
    float4 bv = __ldg(be + gi);
    float4 o;
    o.x = fmaf(xv.x, gv.x, bv.x);
    o.y = fmaf(xv.y, gv.y, bv.y);
    o.z = fmaf(xv.z, gv.z, bv.z);
    o.w = fmaf(xv.w, gv.w, bv.w);
    out[idx] = o;
}

// ---------------------------------------------------------------------------
extern "C" void kernel_launch(void* const* d_in, const int* in_sizes, int n_in,
                              void* d_out, int out_size)
{
    (void)in_sizes; (void)n_in; (void)out_size;
    const float* x   = (const float*)d_in[0];
    const float* psi = (const float*)d_in[1];
    const float* gw1 = (const float*)d_in[2];
    const float* gb1 = (const float*)d_in[3];
    const float* gw2 = (const float*)d_in[4];
    const float* gb2 = (const float*)d_in[5];
    const float* bw1 = (const float*)d_in[6];
    const float* bb1 = (const float*)d_in[7];
    const float* bw2 = (const float*)d_in[8];
    const float* bb2 = (const float*)d_in[9];

    float *tg, *tb, *gm, *bt;
    cudaGetSymbolAddress((void**)&tg, d_tg);
    cudaGetSymbolAddress((void**)&tb, d_tb);
    cudaGetSymbolAddress((void**)&gm, d_gamma);
    cudaGetSymbolAddress((void**)&bt, d_beta);

    cudaFuncSetAttribute(conv_stage,
                         cudaFuncAttributeMaxDynamicSharedMemorySize,
                         CONV_SMEM);

    dim3 cgrid(WW/32, HH/4, BB*2);   // (2, 16, 8) = 256 blocks

    // stage 1: psi -> tg (gamma branch), tb (beta branch), both in one launch
    conv_stage<<<cgrid, 128, CONV_SMEM>>>(psi, psi, gw1, gb1, bw1, bb1, tg, tb);
    // stage 2: tg -> gamma, tb -> beta
    conv_stage<<<cgrid, 128, CONV_SMEM>>>(tg, tb, gw2, gb2, bw2, bb2, gm, bt);

    // FiLM modulation (HBM-bound streaming)
    film_kernel<<<OUT_FLOAT4/256, 256>>>((const float4*)x, (const float4*)gm,
                                         (const float4*)bt, (float4*)d_out);
}

// round 6
// speedup vs baseline: 1.4648x; 1.0031x over previous
#include <cuda_runtime.h>

// Problem constants (fixed shapes per reference setup_inputs)
#define BB    4
#define HH    64
#define WW    64
#define CH    32
#define BANDS 128

#define PIXELS     (BB*HH*WW)            // 16384
#define FEAT_ELEMS (PIXELS*CH)           // 524288 floats (2 MB)

// Scratch (device globals: no allocation allowed)
__device__ float d_tg[FEAT_ELEMS];
__device__ float d_tb[FEAT_ELEMS];
__device__ float d_gamma[FEAT_ELEMS];
__device__ float d_beta[FEAT_ELEMS];

// ---------------------------------------------------------------------------
// packed fp32x2 helpers (sm_100a: 2x fp32 FMA throughput; only via PTX)
// ---------------------------------------------------------------------------
static __device__ __forceinline__ unsigned long long pack2(float a) {
    unsigned int u = __float_as_uint(a);
    unsigned long long r;
    asm("mov.b64 %0, {%1, %1};" : "=l"(r) : "r"(u));
    return r;
}
static __device__ __forceinline__ void ffma2(unsigned long long& d,
                                             unsigned long long a,
                                             unsigned long long b) {
    asm("fma.rn.f32x2 %0, %1, %2, %0;" : "+l"(d) : "l"(a), "l"(b));
}
static __device__ __forceinline__ float lrelu(float v) {
    return (v < 0.0f) ? 0.3f * v : v;
}

// ---------------------------------------------------------------------------
// conv3x3 SAME + bias + LeakyReLU(0.3), C=32->32, NHWC / HWIO.
// One kernel computes BOTH branches of a stage (branch picked by blockIdx.z).
//
// Tile: 32 wide x 4 tall outputs. 128 threads:
//   warp q = tid>>5  -> output channels co = 8q..8q+7
//   lane x = tid&31  -> output column; each thread owns 4 vertical pixels.
// Live set: acc[4][4] u64 (64 regs) + weights 16 u64 (32 regs) + addr ->
// needs ~120 regs. Grid is only 1.73 blocks/SM (grid-limited occupancy), so
// registers are free: __launch_bounds__(128, 1) lets ptxas keep everything
// resident (R5 evidence: at 73 regs ptxas spilled the accumulators to local,
// turning the inner loop into LDL/STL round-trips = the entire 73% stall).
// SMEM: weights [9][32][32] (36.9KB) + input tile [6][34] px, stride 36 fl
// (lane stride 144B: 8-lane LDS.128 phases hit disjoint banks, conflict-free).
// ---------------------------------------------------------------------------
#define TIW       34
#define TIH       6
#define PSTRIDE   36
#define SW_ELEMS  (9*32*32)                          // 9216
#define SIN_ELEMS (TIH*TIW*PSTRIDE)                  // 7344
#define CONV_SMEM ((SW_ELEMS + SIN_ELEMS)*4)         // 66240 B

__global__ void __launch_bounds__(128, 1)
conv_stage(const float* __restrict__ in_g, const float* __restrict__ in_b,
           const float* __restrict__ wg, const float* __restrict__ bg,
           const float* __restrict__ wb, const float* __restrict__ bbias,
           float* __restrict__ out_g, float* __restrict__ out_b)
{
    extern __shared__ float smem[];
    float* s_w  = smem;              // [tap][ci][co], co contiguous
    float* s_in = smem + SW_ELEMS;   // [(r*34 + c)*36 + ci]

    const int tid = threadIdx.x;
    const int x0  = blockIdx.x * 32;
    const int y0  = blockIdx.y * 4;
    const int b   = blockIdx.z & 3;
    const int br  = blockIdx.z >> 2;       // 0 = gamma, 1 = beta

    const float* in   = br ? in_b  : in_g;
    const float* w    = br ? wb    : wg;
    const float* bias = br ? bbias : bg;
    float*       out  = br ? out_b : out_g;

    // ---- stage weights into smem (layout already matches HWIO flat) ----
    {
        const float4* ws = (const float4*)w;
        float4* wd = (float4*)s_w;
        #pragma unroll 1
        for (int i = tid; i < SW_ELEMS/4; i += 128)
            wd[i] = ws[i];
    }

    // ---- stage input tile with halo (6 rows x 34 cols x 32 ch) ----
    #pragma unroll 1
    for (int i = tid; i < TIH*TIW*8; i += 128) {
        int j = i & 7;            // ci4 chunk
        int t = i >> 3;           // pixel index within tile
        int c = t % TIW;
        int r = t / TIW;
        int gx = x0 + c - 1;
        int gy = y0 + r - 1;
        float4 v = make_float4(0.f, 0.f, 0.f, 0.f);
        if (gx >= 0 && gx < WW && gy >= 0 && gy < HH)
            v = *(const float4*)&in[(((b*HH) + gy)*WW + gx)*CH + j*4];
        *(float4*)&s_in[(r*TIW + c)*PSTRIDE + j*4] = v;
    }
    __syncthreads();

    const int q = tid >> 5;       // co-quarter
    const int x = tid & 31;       // output column within tile
    const int co = q << 3;

    unsigned long long acc[4][4];
    #pragma unroll
    for (int o = 0; o < 4; o++)
        #pragma unroll
        for (int k = 0; k < 4; k++) acc[o][k] = 0ull;

    #pragma unroll 1
    for (int kh = 0; kh < 3; kh++) {
        #pragma unroll 1
        for (int c4 = 0; c4 < 8; c4++) {
            #pragma unroll
            for (int kw = 0; kw < 3; kw++) {
                // weights for (kh,kw, ci=4*c4..+3, co..co+7): 16 u64, broadcast LDS
                const ulonglong2* wp = (const ulonglong2*)
                    &s_w[((kh*3 + kw) << 10) + (c4 << 7) + co];
                ulonglong2 wv[4][2];
                #pragma unroll
                for (int ci = 0; ci < 4; ci++) {
                    wv[ci][0] = wp[ci*8];      // 32 floats per ci = 8 ull2
                    wv[ci][1] = wp[ci*8 + 1];
                }
                #pragma unroll
                for (int o = 0; o < 4; o++) {
                    float4 av = *(const float4*)
                        &s_in[((o + kh)*TIW + x + kw)*PSTRIDE + (c4 << 2)];
                    const float* af = (const float*)&av;
                    #pragma unroll
                    for (int ci = 0; ci < 4; ci++) {
                        unsigned long long a2 = pack2(af[ci]);
                        ffma2(acc[o][0], a2, wv[ci][0].x);
                        ffma2(acc[o][1], a2, wv[ci][0].y);
                        ffma2(acc[o][2], a2, wv[ci][1].x);
                        ffma2(acc[o][3], a2, wv[ci][1].y);
                    }
                }
            }
        }
    }

    // ---- epilogue: bias + LeakyReLU, store 4 rows x 8 channels ----
    float bv[8];
    #pragma unroll
    for (int k = 0; k < 8; k++) bv[k] = __ldg(&bias[co + k]);

    #pragma unroll
    for (int o = 0; o < 4; o++) {
        float r[8];
        #pragma unroll
        for (int k = 0; k < 4; k++) {
            unsigned int lo, hi;
            asm("mov.b64 {%0, %1}, %2;" : "=r"(lo), "=r"(hi) : "l"(acc[o][k]));
            r[2*k]   = lrelu(__uint_as_float(lo) + bv[2*k]);
            r[2*k+1] = lrelu(__uint_as_float(hi) + bv[2*k+1]);
        }
        float* op = &out[(((b*HH) + y0 + o)*WW + x0 + x)*CH + co];
        *(float4*)op       = make_float4(r[0], r[1], r[2], r[3]);
        *(float4*)(op + 4) = make_float4(r[4], r[5], r[6], r[7]);
    }
}

// ---------------------------------------------------------------------------
// FiLM: out[b,h,w,band,c] = x * gamma[b,h,w,c] + beta[b,h,w,c]
// Already at HBM roofline (~7.2 TB/s) — unchanged.
// ---------------------------------------------------------------------------
#define OUT_FLOAT4 (BB*HH*WW*BANDS*CH/4)    // 16,777,216

__global__ void __launch_bounds__(256)
film_kernel(const float4* __restrict__ x, const float4* __restrict__ g,
            const float4* __restrict__ be, float4* __restrict__ out)
{
    unsigned int idx = blockIdx.x * 256u + threadIdx.x;
    if (idx >= OUT_FLOAT4) return;
    unsigned int gi = ((idx >> 10) << 3) | (idx & 7u);
    float4 xv = __ldg(x + idx);
    float4 gv = __ldg(g + gi);
    float4 bv = __ldg(be + gi);
    float4 o;
    o.x = fmaf(xv.x, gv.x, bv.x);
    o.y = fmaf(xv.y, gv.y, bv.y);
    o.z = fmaf(xv.z, gv.z, bv.z);
    o.w = fmaf(xv.w, gv.w, bv.w);
    out[idx] = o;
}

// ---------------------------------------------------------------------------
extern "C" void kernel_launch(void* const* d_in, const int* in_sizes, int n_in,
                              void* d_out, int out_size)
{
    (void)in_sizes; (void)n_in; (void)out_size;
    const float* x   = (const float*)d_in[0];
    const float* psi = (const float*)d_in[1];
    const float* gw1 = (const float*)d_in[2];
    const float* gb1 = (const float*)d_in[3];
    const float* gw2 = (const float*)d_in[4];
    const float* gb2 = (const float*)d_in[5];
    const float* bw1 = (const float*)d_in[6];
    const float* bb1 = (const float*)d_in[7];
    const float* bw2 = (const float*)d_in[8];
    const float* bb2 = (const float*)d_in[9];

    float *tg, *tb, *gm, *bt;
    cudaGetSymbolAddress((void**)&tg, d_tg);
    cudaGetSymbolAddress((void**)&tb, d_tb);
    cudaGetSymbolAddress((void**)&gm, d_gamma);
    cudaGetSymbolAddress((void**)&bt, d_beta);

    cudaFuncSetAttribute(conv_stage,
                         cudaFuncAttributeMaxDynamicSharedMemorySize,
                         CONV_SMEM);

    dim3 cgrid(WW/32, HH/4, BB*2);   // (2, 16, 8) = 256 blocks

    // stage 1: psi -> tg (gamma branch), tb (beta branch), both in one launch
    conv_stage<<<cgrid, 128, CONV_SMEM>>>(psi, psi, gw1, gb1, bw1, bb1, tg, tb);
    // stage 2: tg -> gamma, tb -> beta
    conv_stage<<<cgrid, 128, CONV_SMEM>>>(tg, tb, gw2, gb2, bw2, bb2, gm, bt);

    // FiLM modulation (HBM-bound streaming)
    film_kernel<<<OUT_FLOAT4/256, 256>>>((const float4*)x, (const float4*)gm,
                                         (const float4*)bt, (float4*)d_out);
}